// round 16
// baseline (speedup 1.0000x reference)
#include <cuda_runtime.h>
#include <cuda_fp16.h>

#define NN 50000
#define EE 1600000
#define F  128
#define H  4
#define D  32
#define HD 128
#define BUCKET 128   // fixed per-destination bucket capacity (P(deg>128) ~ 1e-40)

// Scratch (allocation-free rule: __device__ globals)
__device__ __half g_h[NN * HD];           // projected features fp16 (L2-resident)
__device__ float g_es[NN * H];            // per-node source logits
__device__ float g_ed[NN * H];            // per-node dest logits
__device__ int   g_cnt[NN];               // per-dst degree (atomic bump)
__device__ int   g_srcsorted[NN * BUCKET];// bucketed src ids, dst-major
__device__ int   g_is64;                  // 1 if edge arrays are int64

__device__ __forceinline__ int edge_at(const void* edges, int i) {
    if (g_is64) return (int)((const long long*)edges)[i];
    return ((const int*)edges)[i];
}

// ---------------------------------------------------------------------------
// K0: zero the degree counters + detect edge dtype
// ---------------------------------------------------------------------------
__global__ void zero_kernel(int n, const void* edges) {
    int i = blockIdx.x * blockDim.x + threadIdx.x;
    if (i < n) g_cnt[i] = 0;
    if (i == 0) {
        const long long* p = (const long long*)edges;
        int ok = 1;
        #pragma unroll
        for (int q = 0; q < 8; q++) {
            long long v = p[q];
            if (v < 0 || v >= NN) ok = 0;
        }
        g_is64 = ok;
    }
}

// ---------------------------------------------------------------------------
// K1 (stream B): HMMA GEMM + fused logits. Register-isolated from the
// latency-bound edge path by running on a forked stream.
// ---------------------------------------------------------------------------
__global__ __launch_bounds__(256) void gemm_kernel(
    const float* __restrict__ x, const float* __restrict__ W,
    const float* __restrict__ a_src, const float* __restrict__ a_dst, int n)
{
    __shared__ __half ws[128][136];    // [k][n], 272B row stride
    __shared__ float as_s[128];
    __shared__ float ad_s[128];

    int tid = threadIdx.x;
    int warp = tid >> 5;
    int lane = tid & 31;

    {
        const float4* W4 = (const float4*)W;
        #pragma unroll
        for (int q = 0; q < 16; q++) {
            int linear = q * 256 + tid;
            int row = linear >> 5;
            int c4  = linear & 31;
            float4 v = W4[linear];
            *(__half2*)&ws[row][c4 * 4]     = __floats2half2_rn(v.x, v.y);
            *(__half2*)&ws[row][c4 * 4 + 2] = __floats2half2_rn(v.z, v.w);
        }
        if (tid < 128) as_s[tid] = a_src[tid];
        else           ad_s[tid - 128] = a_dst[tid - 128];
    }
    __syncthreads();

    int mbase = blockIdx.x * 128 + warp * 16;
    int r0 = mbase + (lane >> 2);
    int r1 = r0 + 8;
    int c0 = (lane & 3) * 2;
    bool v0 = r0 < n, v1 = r1 < n;

    float acc[16][4];
    #pragma unroll
    for (int j = 0; j < 16; j++)
        #pragma unroll
        for (int q = 0; q < 4; q++) acc[j][q] = 0.f;

    const float* xr0 = x + (size_t)(v0 ? r0 : 0) * 128;
    const float* xr1 = x + (size_t)(v1 ? r1 : 0) * 128;
    int brow = lane & 15;

    #pragma unroll
    for (int t = 0; t < 8; t++) {
        int cb = t * 16 + c0;
        float2 f00 = v0 ? *(const float2*)(xr0 + cb)     : make_float2(0.f, 0.f);
        float2 f01 = v0 ? *(const float2*)(xr0 + cb + 8) : make_float2(0.f, 0.f);
        float2 f10 = v1 ? *(const float2*)(xr1 + cb)     : make_float2(0.f, 0.f);
        float2 f11 = v1 ? *(const float2*)(xr1 + cb + 8) : make_float2(0.f, 0.f);

        __half2 ha0 = __floats2half2_rn(f00.x, f00.y);
        __half2 ha1 = __floats2half2_rn(f10.x, f10.y);
        __half2 ha2 = __floats2half2_rn(f01.x, f01.y);
        __half2 ha3 = __floats2half2_rn(f11.x, f11.y);
        unsigned a0 = *(unsigned*)&ha0;
        unsigned a1 = *(unsigned*)&ha1;
        unsigned a2 = *(unsigned*)&ha2;
        unsigned a3 = *(unsigned*)&ha3;

        #pragma unroll
        for (int j = 0; j < 16; j++) {
            unsigned b0, b1;
            unsigned baddr = (unsigned)__cvta_generic_to_shared(
                &ws[t * 16 + brow][j * 8]);
            asm volatile(
                "ldmatrix.sync.aligned.m8n8.x2.trans.shared.b16 {%0,%1}, [%2];"
                : "=r"(b0), "=r"(b1) : "r"(baddr));
            asm volatile(
                "mma.sync.aligned.m16n8k16.row.col.f32.f16.f16.f32 "
                "{%0,%1,%2,%3}, {%4,%5,%6,%7}, {%8,%9}, {%0,%1,%2,%3};"
                : "+f"(acc[j][0]), "+f"(acc[j][1]), "+f"(acc[j][2]), "+f"(acc[j][3])
                : "r"(a0), "r"(a1), "r"(a2), "r"(a3), "r"(b0), "r"(b1));
        }
    }

    if (v0) {
        #pragma unroll
        for (int j = 0; j < 16; j++)
            *(__half2*)&g_h[(size_t)r0 * HD + j * 8 + c0] =
                __floats2half2_rn(acc[j][0], acc[j][1]);
    }
    if (v1) {
        #pragma unroll
        for (int j = 0; j < 16; j++)
            *(__half2*)&g_h[(size_t)r1 * HD + j * 8 + c0] =
                __floats2half2_rn(acc[j][2], acc[j][3]);
    }

    // Fused logits
    float4 es0 = make_float4(0,0,0,0), ed0 = es0, es1 = es0, ed1 = es0;
    #pragma unroll
    for (int hd = 0; hd < 4; hd++) {
        float s0 = 0.f, d0 = 0.f, s1 = 0.f, d1 = 0.f;
        #pragma unroll
        for (int jj = 0; jj < 4; jj++) {
            int j = hd * 4 + jj;
            float wa = as_s[j * 8 + c0];
            float wb = as_s[j * 8 + c0 + 1];
            float va = ad_s[j * 8 + c0];
            float vb = ad_s[j * 8 + c0 + 1];
            s0 = fmaf(acc[j][0], wa, fmaf(acc[j][1], wb, s0));
            d0 = fmaf(acc[j][0], va, fmaf(acc[j][1], vb, d0));
            s1 = fmaf(acc[j][2], wa, fmaf(acc[j][3], wb, s1));
            d1 = fmaf(acc[j][2], va, fmaf(acc[j][3], vb, d1));
        }
        ((float*)&es0)[hd] = s0; ((float*)&ed0)[hd] = d0;
        ((float*)&es1)[hd] = s1; ((float*)&ed1)[hd] = d1;
    }
    #pragma unroll
    for (int off = 1; off <= 2; off <<= 1) {
        #pragma unroll
        for (int q = 0; q < 4; q++) {
            ((float*)&es0)[q] += __shfl_xor_sync(0xffffffffu, ((float*)&es0)[q], off);
            ((float*)&ed0)[q] += __shfl_xor_sync(0xffffffffu, ((float*)&ed0)[q], off);
            ((float*)&es1)[q] += __shfl_xor_sync(0xffffffffu, ((float*)&es1)[q], off);
            ((float*)&ed1)[q] += __shfl_xor_sync(0xffffffffu, ((float*)&ed1)[q], off);
        }
    }
    if ((lane & 3) == 0) {
        if (v0) {
            *(float4*)&g_es[r0 * H] = es0;
            *(float4*)&g_ed[r0 * H] = ed0;
        }
        if (v1) {
            *(float4*)&g_es[r1 * H] = es1;
            *(float4*)&g_ed[r1 * H] = ed1;
        }
    }
}

// ---------------------------------------------------------------------------
// K2: ONE-PASS bucketed CSR build. pos = atomicAdd(cnt[dst]); write src into
// the dst's fixed 128-slot bucket. No histogram, no scan.
// ---------------------------------------------------------------------------
__global__ void scatter_kernel(const void* __restrict__ edge_src,
                               const void* __restrict__ edge_dst, int e)
{
    int i4 = (blockIdx.x * blockDim.x + threadIdx.x) * 4;
    if (i4 + 3 < e) {
        int d[4], s[4];
        if (g_is64) {
            longlong2 p0 = ((const longlong2*)edge_dst)[i4 >> 1];
            longlong2 p1 = ((const longlong2*)edge_dst)[(i4 >> 1) + 1];
            d[0] = (int)p0.x; d[1] = (int)p0.y; d[2] = (int)p1.x; d[3] = (int)p1.y;
            longlong2 q0 = ((const longlong2*)edge_src)[i4 >> 1];
            longlong2 q1 = ((const longlong2*)edge_src)[(i4 >> 1) + 1];
            s[0] = (int)q0.x; s[1] = (int)q0.y; s[2] = (int)q1.x; s[3] = (int)q1.y;
        } else {
            int4 p = ((const int4*)edge_dst)[i4 >> 2];
            d[0] = p.x; d[1] = p.y; d[2] = p.z; d[3] = p.w;
            int4 q = ((const int4*)edge_src)[i4 >> 2];
            s[0] = q.x; s[1] = q.y; s[2] = q.z; s[3] = q.w;
        }
        #pragma unroll
        for (int q = 0; q < 4; q++) {
            int pos = atomicAdd(&g_cnt[d[q]], 1);
            if (pos < BUCKET)
                g_srcsorted[d[q] * BUCKET + pos] = s[q];
        }
    } else {
        for (int i = i4; i < e; i++) {
            int dst = edge_at(edge_dst, i);
            int pos = atomicAdd(&g_cnt[dst], 1);
            if (pos < BUCKET)
                g_srcsorted[dst * BUCKET + pos] = edge_at(edge_src, i);
        }
    }
}

// ---------------------------------------------------------------------------
// K3: aggregation. One warp per destination node; bucket rows are
// 512B-aligned. fp32 accumulators over fp16 gathered rows, no output atomics.
// ---------------------------------------------------------------------------
__global__ void agg_kernel(const float* __restrict__ bias,
                           float* __restrict__ out, int n)
{
    int gw = (blockIdx.x * blockDim.x + threadIdx.x) >> 5;
    int lane = threadIdx.x & 31;
    if (gw >= n) return;
    int hd = lane >> 3;

    float edv = g_ed[gw * H + hd];
    int cnt = g_cnt[gw];
    if (cnt > BUCKET) cnt = BUCKET;
    const int* bucket = &g_srcsorted[gw * BUCKET];

    float4 acc = make_float4(0.f, 0.f, 0.f, 0.f);
    float denom = 0.f;
    const uint2* h2 = (const uint2*)g_h;

    #pragma unroll 8
    for (int i = 0; i < cnt; ++i) {
        int src = bucket[i];
        float ev = g_es[src * H + hd] + edv;
        ev = fmaxf(ev, 0.2f * ev);          // LeakyReLU(0.2)
        float al = __expf(ev);
        denom += al;
        uint2 raw = h2[(size_t)src * 32 + lane];
        float2 f0 = __half22float2(*(__half2*)&raw.x);
        float2 f1 = __half22float2(*(__half2*)&raw.y);
        acc.x = fmaf(al, f0.x, acc.x);
        acc.y = fmaf(al, f0.y, acc.y);
        acc.z = fmaf(al, f1.x, acc.z);
        acc.w = fmaf(al, f1.y, acc.w);
    }

    float inv = denom > 0.f ? 1.0f / denom : 0.f;
    float4 bv = ((const float4*)bias)[lane];
    float4 o;
    o.x = fmaf(acc.x, inv, bv.x);
    o.y = fmaf(acc.y, inv, bv.y);
    o.z = fmaf(acc.z, inv, bv.z);
    o.w = fmaf(acc.w, inv, bv.w);
    ((float4*)out)[(size_t)gw * 32 + lane] = o;
}

// ---------------------------------------------------------------------------
// Fork-join: GEMM on a side stream overlaps zero->scatter; join before agg.
// ---------------------------------------------------------------------------
extern "C" void kernel_launch(void* const* d_in, const int* in_sizes, int n_in,
                              void* d_out, int out_size)
{
    const float* x      = (const float*)d_in[0];
    const float* W      = (const float*)d_in[1];
    const float* a_src  = (const float*)d_in[2];
    const float* a_dst  = (const float*)d_in[3];
    const float* bias   = (const float*)d_in[4];
    const void*  esrc   = d_in[5];
    const void*  edst   = d_in[6];
    float* out = (float*)d_out;

    int n = in_sizes[0] / F;     // 50000
    int e = in_sizes[5];         // 1600000
    int gemm_blocks = (n + 127) / 128;        // 391

    cudaStream_t s2;
    cudaEvent_t evFork, evJoin;
    cudaStreamCreateWithFlags(&s2, cudaStreamNonBlocking);
    cudaEventCreateWithFlags(&evFork, cudaEventDisableTiming);
    cudaEventCreateWithFlags(&evJoin, cudaEventDisableTiming);

    cudaEventRecord(evFork, 0);
    cudaStreamWaitEvent(s2, evFork, 0);
    gemm_kernel<<<gemm_blocks, 256, 0, s2>>>(x, W, a_src, a_dst, n);

    zero_kernel<<<(n + 255) / 256, 256>>>(n, edst);
    scatter_kernel<<<(e / 4 + 255) / 256, 256>>>(esrc, edst, e);

    cudaEventRecord(evJoin, s2);
    cudaStreamWaitEvent(0, evJoin, 0);
    agg_kernel<<<(n * 32 + 255) / 256, 256>>>(bias, out, n);
}

// round 17
// speedup vs baseline: 1.3135x; 1.3135x over previous
#include <cuda_runtime.h>
#include <cuda_fp16.h>

#define NN 50000
#define EE 1600000
#define F  128
#define H  4
#define D  32
#define HD 128

#define SCAN_BLK 256
#define SCAN_NB  ((NN + SCAN_BLK - 1) / SCAN_BLK)   // 196

// Scratch (allocation-free rule: __device__ globals)
__device__ __half g_h[NN * HD];         // projected features fp16, 12.8 MB (L2-resident)
__device__ float g_es[NN * H];          // per-node source logits
__device__ float g_ed[NN * H];          // per-node dest logits
__device__ int   g_count[NN];           // in-degree histogram
__device__ int   g_rowstart[NN + 1];    // CSR row offsets (by dst)
__device__ int   g_cursor[NN];          // scatter cursors
__device__ int   g_srcsorted[EE];       // src node per edge, grouped by dst (packed!)
__device__ int   g_is64;                // 1 if edge arrays are int64
__device__ int   g_bsum[SCAN_NB];       // per-block partial sums

__device__ __forceinline__ int edge_at(const void* edges, int i) {
    if (g_is64) return (int)((const long long*)edges)[i];
    return ((const int*)edges)[i];
}

// ---------------------------------------------------------------------------
// K0: zero the histogram + detect edge dtype
// ---------------------------------------------------------------------------
__global__ void zero_kernel(int n, const void* edges) {
    int i = blockIdx.x * blockDim.x + threadIdx.x;
    if (i < n) g_count[i] = 0;
    if (i == 0) {
        const long long* p = (const long long*)edges;
        int ok = 1;
        #pragma unroll
        for (int q = 0; q < 8; q++) {
            long long v = p[q];
            if (v < 0 || v >= NN) ok = 0;
        }
        g_is64 = ok;
    }
}

// ---------------------------------------------------------------------------
// K1: HYBRID kernel. Blocks [0, gemm_blocks): HMMA GEMM + fused logits.
//     Blocks [gemm_blocks, ...): in-degree histogram, 4 edges/thread.
//     (hist is cheap + latency-bound; tolerates the GEMM register footprint)
// ---------------------------------------------------------------------------
__global__ __launch_bounds__(256) void gemm_hist_kernel(
    const float* __restrict__ x, const float* __restrict__ W,
    const float* __restrict__ a_src, const float* __restrict__ a_dst, int n,
    const void* __restrict__ edge_dst, int e, int gemm_blocks)
{
    __shared__ __half ws[128][136];    // [k][n], 272B row stride
    __shared__ float as_s[128];
    __shared__ float ad_s[128];

    int tid = threadIdx.x;

    if (blockIdx.x >= gemm_blocks) {
        // ----- histogram part: 4 edges per thread, vectorized loads -----
        int hb = blockIdx.x - gemm_blocks;
        int i4 = (hb * 256 + tid) * 4;
        if (i4 + 3 < e) {
            int d0, d1, d2, d3;
            if (g_is64) {
                longlong2 p0 = ((const longlong2*)edge_dst)[i4 >> 1];
                longlong2 p1 = ((const longlong2*)edge_dst)[(i4 >> 1) + 1];
                d0 = (int)p0.x; d1 = (int)p0.y; d2 = (int)p1.x; d3 = (int)p1.y;
            } else {
                int4 p = ((const int4*)edge_dst)[i4 >> 2];
                d0 = p.x; d1 = p.y; d2 = p.z; d3 = p.w;
            }
            atomicAdd(&g_count[d0], 1);
            atomicAdd(&g_count[d1], 1);
            atomicAdd(&g_count[d2], 1);
            atomicAdd(&g_count[d3], 1);
        } else {
            for (int i = i4; i < e; i++) atomicAdd(&g_count[edge_at(edge_dst, i)], 1);
        }
        return;
    }

    // ----- GEMM part -----
    int warp = tid >> 5;
    int lane = tid & 31;

    {
        const float4* W4 = (const float4*)W;
        #pragma unroll
        for (int q = 0; q < 16; q++) {
            int linear = q * 256 + tid;
            int row = linear >> 5;
            int c4  = linear & 31;
            float4 v = W4[linear];
            *(__half2*)&ws[row][c4 * 4]     = __floats2half2_rn(v.x, v.y);
            *(__half2*)&ws[row][c4 * 4 + 2] = __floats2half2_rn(v.z, v.w);
        }
        if (tid < 128) as_s[tid] = a_src[tid];
        else           ad_s[tid - 128] = a_dst[tid - 128];
    }
    __syncthreads();

    int mbase = blockIdx.x * 128 + warp * 16;
    int r0 = mbase + (lane >> 2);
    int r1 = r0 + 8;
    int c0 = (lane & 3) * 2;
    bool v0 = r0 < n, v1 = r1 < n;

    float acc[16][4];
    #pragma unroll
    for (int j = 0; j < 16; j++)
        #pragma unroll
        for (int q = 0; q < 4; q++) acc[j][q] = 0.f;

    const float* xr0 = x + (size_t)(v0 ? r0 : 0) * 128;
    const float* xr1 = x + (size_t)(v1 ? r1 : 0) * 128;
    int brow = lane & 15;

    #pragma unroll
    for (int t = 0; t < 8; t++) {
        int cb = t * 16 + c0;
        float2 f00 = v0 ? *(const float2*)(xr0 + cb)     : make_float2(0.f, 0.f);
        float2 f01 = v0 ? *(const float2*)(xr0 + cb + 8) : make_float2(0.f, 0.f);
        float2 f10 = v1 ? *(const float2*)(xr1 + cb)     : make_float2(0.f, 0.f);
        float2 f11 = v1 ? *(const float2*)(xr1 + cb + 8) : make_float2(0.f, 0.f);

        __half2 ha0 = __floats2half2_rn(f00.x, f00.y);
        __half2 ha1 = __floats2half2_rn(f10.x, f10.y);
        __half2 ha2 = __floats2half2_rn(f01.x, f01.y);
        __half2 ha3 = __floats2half2_rn(f11.x, f11.y);
        unsigned a0 = *(unsigned*)&ha0;
        unsigned a1 = *(unsigned*)&ha1;
        unsigned a2 = *(unsigned*)&ha2;
        unsigned a3 = *(unsigned*)&ha3;

        #pragma unroll
        for (int j = 0; j < 16; j++) {
            unsigned b0, b1;
            unsigned baddr = (unsigned)__cvta_generic_to_shared(
                &ws[t * 16 + brow][j * 8]);
            asm volatile(
                "ldmatrix.sync.aligned.m8n8.x2.trans.shared.b16 {%0,%1}, [%2];"
                : "=r"(b0), "=r"(b1) : "r"(baddr));
            asm volatile(
                "mma.sync.aligned.m16n8k16.row.col.f32.f16.f16.f32 "
                "{%0,%1,%2,%3}, {%4,%5,%6,%7}, {%8,%9}, {%0,%1,%2,%3};"
                : "+f"(acc[j][0]), "+f"(acc[j][1]), "+f"(acc[j][2]), "+f"(acc[j][3])
                : "r"(a0), "r"(a1), "r"(a2), "r"(a3), "r"(b0), "r"(b1));
        }
    }

    if (v0) {
        #pragma unroll
        for (int j = 0; j < 16; j++)
            *(__half2*)&g_h[(size_t)r0 * HD + j * 8 + c0] =
                __floats2half2_rn(acc[j][0], acc[j][1]);
    }
    if (v1) {
        #pragma unroll
        for (int j = 0; j < 16; j++)
            *(__half2*)&g_h[(size_t)r1 * HD + j * 8 + c0] =
                __floats2half2_rn(acc[j][2], acc[j][3]);
    }

    // Fused logits
    float4 es0 = make_float4(0,0,0,0), ed0 = es0, es1 = es0, ed1 = es0;
    #pragma unroll
    for (int hd = 0; hd < 4; hd++) {
        float s0 = 0.f, d0 = 0.f, s1 = 0.f, d1 = 0.f;
        #pragma unroll
        for (int jj = 0; jj < 4; jj++) {
            int j = hd * 4 + jj;
            float wa = as_s[j * 8 + c0];
            float wb = as_s[j * 8 + c0 + 1];
            float va = ad_s[j * 8 + c0];
            float vb = ad_s[j * 8 + c0 + 1];
            s0 = fmaf(acc[j][0], wa, fmaf(acc[j][1], wb, s0));
            d0 = fmaf(acc[j][0], va, fmaf(acc[j][1], vb, d0));
            s1 = fmaf(acc[j][2], wa, fmaf(acc[j][3], wb, s1));
            d1 = fmaf(acc[j][2], va, fmaf(acc[j][3], vb, d1));
        }
        ((float*)&es0)[hd] = s0; ((float*)&ed0)[hd] = d0;
        ((float*)&es1)[hd] = s1; ((float*)&ed1)[hd] = d1;
    }
    #pragma unroll
    for (int off = 1; off <= 2; off <<= 1) {
        #pragma unroll
        for (int q = 0; q < 4; q++) {
            ((float*)&es0)[q] += __shfl_xor_sync(0xffffffffu, ((float*)&es0)[q], off);
            ((float*)&ed0)[q] += __shfl_xor_sync(0xffffffffu, ((float*)&ed0)[q], off);
            ((float*)&es1)[q] += __shfl_xor_sync(0xffffffffu, ((float*)&es1)[q], off);
            ((float*)&ed1)[q] += __shfl_xor_sync(0xffffffffu, ((float*)&ed1)[q], off);
        }
    }
    if ((lane & 3) == 0) {
        if (v0) {
            *(float4*)&g_es[r0 * H] = es0;
            *(float4*)&g_ed[r0 * H] = ed0;
        }
        if (v1) {
            *(float4*)&g_es[r1 * H] = es1;
            *(float4*)&g_ed[r1 * H] = ed1;
        }
    }
}

// ---------------------------------------------------------------------------
// K2a: per-block partial sums of counts
// ---------------------------------------------------------------------------
__global__ __launch_bounds__(SCAN_BLK) void scan_partial(int n) {
    __shared__ int red[8];
    int i = blockIdx.x * SCAN_BLK + threadIdx.x;
    int v = (i < n) ? g_count[i] : 0;
    #pragma unroll
    for (int off = 16; off >= 1; off >>= 1)
        v += __shfl_down_sync(0xffffffffu, v, off);
    if ((threadIdx.x & 31) == 0) red[threadIdx.x >> 5] = v;
    __syncthreads();
    if (threadIdx.x == 0) {
        int s = 0;
        #pragma unroll
        for (int q = 0; q < 8; q++) s += red[q];
        g_bsum[blockIdx.x] = s;
    }
}

// ---------------------------------------------------------------------------
// K2b: per-block scan; each block redundantly reduces the block sums for its
// own offset (196 loads, trivial) -> rowstart, cursor. Also writes total.
// ---------------------------------------------------------------------------
__global__ __launch_bounds__(SCAN_BLK) void scan_final(int n, int nb) {
    __shared__ int sh[SCAN_BLK];
    __shared__ int red_pref[8], red_tot[8];
    int t = threadIdx.x;

    int vp = (t < nb && t < blockIdx.x) ? g_bsum[t] : 0;
    int vt = (t < nb) ? g_bsum[t] : 0;
    #pragma unroll
    for (int off = 16; off >= 1; off >>= 1) {
        vp += __shfl_down_sync(0xffffffffu, vp, off);
        vt += __shfl_down_sync(0xffffffffu, vt, off);
    }
    if ((t & 31) == 0) { red_pref[t >> 5] = vp; red_tot[t >> 5] = vt; }

    int i = blockIdx.x * SCAN_BLK + t;
    int v = (i < n) ? g_count[i] : 0;
    sh[t] = v;
    __syncthreads();

    int boff = red_pref[0] + red_pref[1] + red_pref[2] + red_pref[3]
             + red_pref[4] + red_pref[5] + red_pref[6] + red_pref[7];
    int total = red_tot[0] + red_tot[1] + red_tot[2] + red_tot[3]
              + red_tot[4] + red_tot[5] + red_tot[6] + red_tot[7];

    #pragma unroll
    for (int off = 1; off < SCAN_BLK; off <<= 1) {
        int w = (t >= off) ? sh[t - off] : 0;
        __syncthreads();
        sh[t] += w;
        __syncthreads();
    }
    if (i < n) {
        int val = boff + sh[t] - v;  // exclusive prefix
        g_rowstart[i] = val;
        g_cursor[i]   = val;
        if (i == n - 1) g_rowstart[n] = total;
    }
}

// ---------------------------------------------------------------------------
// K3: scatter edges into dst-grouped order, 4 edges per thread
// ---------------------------------------------------------------------------
__global__ void scatter_kernel(const void* __restrict__ edge_src,
                               const void* __restrict__ edge_dst, int e)
{
    int i4 = (blockIdx.x * blockDim.x + threadIdx.x) * 4;
    if (i4 + 3 < e) {
        int d[4], s[4];
        if (g_is64) {
            longlong2 p0 = ((const longlong2*)edge_dst)[i4 >> 1];
            longlong2 p1 = ((const longlong2*)edge_dst)[(i4 >> 1) + 1];
            d[0] = (int)p0.x; d[1] = (int)p0.y; d[2] = (int)p1.x; d[3] = (int)p1.y;
            longlong2 q0 = ((const longlong2*)edge_src)[i4 >> 1];
            longlong2 q1 = ((const longlong2*)edge_src)[(i4 >> 1) + 1];
            s[0] = (int)q0.x; s[1] = (int)q0.y; s[2] = (int)q1.x; s[3] = (int)q1.y;
        } else {
            int4 p = ((const int4*)edge_dst)[i4 >> 2];
            d[0] = p.x; d[1] = p.y; d[2] = p.z; d[3] = p.w;
            int4 q = ((const int4*)edge_src)[i4 >> 2];
            s[0] = q.x; s[1] = q.y; s[2] = q.z; s[3] = q.w;
        }
        #pragma unroll
        for (int q = 0; q < 4; q++) {
            int pos = atomicAdd(&g_cursor[d[q]], 1);
            g_srcsorted[pos] = s[q];
        }
    } else {
        for (int i = i4; i < e; i++) {
            int dst = edge_at(edge_dst, i);
            int pos = atomicAdd(&g_cursor[dst], 1);
            g_srcsorted[pos] = edge_at(edge_src, i);
        }
    }
}

// ---------------------------------------------------------------------------
// K4: aggregation. One warp per destination node, fp32 accumulators over
// fp16 gathered rows, no output atomics. (measured-best form)
// ---------------------------------------------------------------------------
__global__ void agg_kernel(const float* __restrict__ bias,
                           float* __restrict__ out, int n)
{
    int gw = (blockIdx.x * blockDim.x + threadIdx.x) >> 5;
    int lane = threadIdx.x & 31;
    if (gw >= n) return;
    int hd = lane >> 3;

    float edv = g_ed[gw * H + hd];
    int start = g_rowstart[gw];
    int end   = g_rowstart[gw + 1];

    float4 acc = make_float4(0.f, 0.f, 0.f, 0.f);
    float denom = 0.f;
    const uint2* h2 = (const uint2*)g_h;

    #pragma unroll 8
    for (int i = start; i < end; ++i) {
        int src = g_srcsorted[i];
        float ev = g_es[src * H + hd] + edv;
        ev = fmaxf(ev, 0.2f * ev);          // LeakyReLU(0.2)
        float al = __expf(ev);
        denom += al;
        uint2 raw = h2[(size_t)src * 32 + lane];
        float2 f0 = __half22float2(*(__half2*)&raw.x);
        float2 f1 = __half22float2(*(__half2*)&raw.y);
        acc.x = fmaf(al, f0.x, acc.x);
        acc.y = fmaf(al, f0.y, acc.y);
        acc.z = fmaf(al, f1.x, acc.z);
        acc.w = fmaf(al, f1.y, acc.w);
    }

    float inv = denom > 0.f ? 1.0f / denom : 0.f;
    float4 bv = ((const float4*)bias)[lane];
    float4 o;
    o.x = fmaf(acc.x, inv, bv.x);
    o.y = fmaf(acc.y, inv, bv.y);
    o.z = fmaf(acc.z, inv, bv.z);
    o.w = fmaf(acc.w, inv, bv.w);
    ((float4*)out)[(size_t)gw * 32 + lane] = o;
}

// ---------------------------------------------------------------------------
extern "C" void kernel_launch(void* const* d_in, const int* in_sizes, int n_in,
                              void* d_out, int out_size)
{
    const float* x      = (const float*)d_in[0];
    const float* W      = (const float*)d_in[1];
    const float* a_src  = (const float*)d_in[2];
    const float* a_dst  = (const float*)d_in[3];
    const float* bias   = (const float*)d_in[4];
    const void*  esrc   = d_in[5];
    const void*  edst   = d_in[6];
    float* out = (float*)d_out;

    int n = in_sizes[0] / F;     // 50000
    int e = in_sizes[5];         // 1600000
    int nb = (n + SCAN_BLK - 1) / SCAN_BLK;  // 196

    int gemm_blocks = (n + 127) / 128;       // 391
    int hist_blocks = (e / 4 + 255) / 256;   // 1563

    zero_kernel<<<(n + 255) / 256, 256>>>(n, edst);
    gemm_hist_kernel<<<gemm_blocks + hist_blocks, 256>>>(
        x, W, a_src, a_dst, n, edst, e, gemm_blocks);
    scan_partial<<<nb, SCAN_BLK>>>(n);
    scan_final<<<nb, SCAN_BLK>>>(n, nb);
    scatter_kernel<<<(e / 4 + 255) / 256, 256>>>(esrc, edst, e);
    agg_kernel<<<(n * 32 + 255) / 256, 256>>>(bias, out, n);
}